// round 9
// baseline (speedup 1.0000x reference)
#include <cuda_runtime.h>
#include <stdint.h>

#define BATCH 128
#define NANCH 16800
#define NQ 4200               // float4 per row
#define CHUNKS 8
#define CQ 525                // float4 per chunk
#define T 256
#define NW (T / 32)           // 8 warps
#define NEL 3                 // ceil(CQ / T)
#define NEG_RATIO 3
#define SCALE_XY 10.0f
#define SCALE_WH 5.0f
#define CAP 4096
#define P0F 1.4f
#define P0BITS 0x3FB33333u    // __float_as_uint(1.4f)
#define FLT_EPS_ 1.1920929e-07f

// Cross-block scratch (allocation-free rule: __device__ globals; zero-init, reset per replay)
__device__ float g_row_lossb[BATCH];
__device__ float g_row_bcepos[BATCH];
__device__ float g_row_lossl[BATCH];
__device__ int   g_row_posn[BATCH];
__device__ int   g_cand_n[BATCH];
__device__ int   g_row_ovf[BATCH];
__device__ int   g_rowdone[BATCH];
__device__ int   g_done = 0;
__device__ float g_cand[BATCH * CAP];   // 2 MB

__device__ __forceinline__ float warp_sum(float v) {
    #pragma unroll
    for (int o = 16; o > 0; o >>= 1) v += __shfl_down_sync(0xFFFFFFFFu, v, o);
    return v;
}
__device__ __forceinline__ int warp_sum_i(int v) {
    #pragma unroll
    for (int o = 16; o > 0; o >>= 1) v += __shfl_down_sync(0xFFFFFFFFu, v, o);
    return v;
}
__device__ __forceinline__ unsigned warp_max_u(unsigned v) {
    #pragma unroll
    for (int o = 16; o > 0; o >>= 1) {
        unsigned u = __shfl_down_sync(0xFFFFFFFFu, v, o);
        v = (u > v) ? u : v;
    }
    return v;
}
__device__ __forceinline__ float bce_of(float x, float y) {
    return fmaxf(x, 0.f) - x * y + __logf(1.f + __expf(-fabsf(x)));
}

__global__ __launch_bounds__(T)
void od_main(const float* __restrict__ pbboxs,
             const float* __restrict__ plabels,
             const float* __restrict__ gbboxs,
             const float* __restrict__ glabels,
             const float* __restrict__ ancs,
             float* __restrict__ out, int out_size) {
    const int row  = blockIdx.y;
    const int tid  = threadIdx.x;
    const int lane = tid & 31;
    const int wid  = tid >> 5;
    const int qbase = blockIdx.x * CQ;

    __shared__ float    s_wf[NW], s_wf2[NW];
    __shared__ int      s_wi[NW];
    __shared__ int      s_sel, s_last;
    __shared__ unsigned s_lo, s_hi;
    __shared__ float    s_top;
    __shared__ float    s_red[NW * 3];

    const float4* pl4 = (const float4*)(plabels + (size_t)row * NANCH);
    const float4* gl4 = (const float4*)(glabels + (size_t)row * NANCH);
    const float4* pb  = (const float4*)pbboxs + (size_t)row * NANCH;
    const float4* gb  = (const float4*)gbboxs + (size_t)row * NANCH;
    const float4* an  = (const float4*)ancs;

    // ================= Streaming phase =================
    float bcv[NEL * 4];
    unsigned cm = 0;                      // candidate bit per element
    float acc_sl1 = 0.f, acc_bce = 0.f;
    int cnt = 0;

    #pragma unroll
    for (int it = 0; it < NEL; it++) {
        const int loc = tid + it * T;
        const int i4  = qbase + loc;
        const bool valid = (loc < CQ);
        float4 xv = valid ? pl4[i4] : make_float4(0.f, 0.f, 0.f, 0.f);
        float4 yv = valid ? gl4[i4] : make_float4(0.f, 0.f, 0.f, 0.f);
        #pragma unroll
        for (int c = 0; c < 4; c++) {
            float x = (c == 0) ? xv.x : (c == 1) ? xv.y : (c == 2) ? xv.z : xv.w;
            float y = (c == 0) ? yv.x : (c == 1) ? yv.y : (c == 2) ? yv.z : yv.w;
            float bce = bce_of(x, y);     // invalid lanes: x=y=0 -> bce=ln2 < P0, y=0 -> not pos
            if (y > 0.f) {
                const int i = i4 * 4 + c;
                float4 p = pb[i];
                float4 g = gb[i];
                float4 a = an[i];
                float inv_az = 1.f / a.z;
                float inv_aw = 1.f / a.w;
                float d0 = p.x - SCALE_XY * (g.x - a.x) * inv_az;
                float d1 = p.y - SCALE_XY * (g.y - a.y) * inv_aw;
                float d2 = p.z - SCALE_WH * __logf(g.z * inv_az);
                float d3 = p.w - SCALE_WH * __logf(g.w * inv_aw);
                float sl1 = 0.f, ad;
                ad = fabsf(d0); sl1 += (ad < 1.f) ? 0.5f * d0 * d0 : ad - 0.5f;
                ad = fabsf(d1); sl1 += (ad < 1.f) ? 0.5f * d1 * d1 : ad - 0.5f;
                ad = fabsf(d2); sl1 += (ad < 1.f) ? 0.5f * d2 * d2 : ad - 0.5f;
                ad = fabsf(d3); sl1 += (ad < 1.f) ? 0.5f * d3 * d3 : ad - 0.5f;
                acc_sl1 += sl1;
                acc_bce += bce;
                cnt++;
            } else if (bce >= P0F) {
                cm |= 1u << (it * 4 + c);
            }
            bcv[it * 4 + c] = bce;
        }
    }

    // warp-level candidate compaction: ONE global atomic per warp
    {
        unsigned mks[NEL * 4];
        int wcnt = 0;
        #pragma unroll
        for (int e = 0; e < NEL * 4; e++) {
            mks[e] = __ballot_sync(0xFFFFFFFFu, (cm >> e) & 1u);
            wcnt += __popc(mks[e]);
        }
        if (wcnt > 0) {
            int base = 0;
            if (lane == 0) base = atomicAdd(&g_cand_n[row], wcnt);
            base = __shfl_sync(0xFFFFFFFFu, base, 0);
            float* dst = g_cand + (size_t)row * CAP;
            int off = base;
            #pragma unroll
            for (int e = 0; e < NEL * 4; e++) {
                if ((cm >> e) & 1u) {
                    const int pi = off + __popc(mks[e] & ((1u << lane) - 1u));
                    if (pi < CAP) dst[pi] = bcv[e];
                    else g_row_ovf[row] = 1;
                }
                off += __popc(mks[e]);
            }
        }
    }

    // row scalar accumulation: block reduce -> 3 global atomics
    {
        float w1 = warp_sum(acc_sl1);
        float w2 = warp_sum(acc_bce);
        int   w3 = warp_sum_i(cnt);
        if (lane == 0) { s_wf[wid] = w1; s_wf2[wid] = w2; s_wi[wid] = w3; }
    }
    __syncthreads();
    if (tid == 0) {
        float s1 = 0.f, s2 = 0.f; int s3 = 0;
        #pragma unroll
        for (int i = 0; i < NW; i++) { s1 += s_wf[i]; s2 += s_wf2[i]; s3 += s_wi[i]; }
        if (s1 != 0.f) atomicAdd(&g_row_lossb[row], s1);
        if (s2 != 0.f) atomicAdd(&g_row_bcepos[row], s2);
        if (s3 != 0)   atomicAdd(&g_row_posn[row], s3);
        __threadfence();
        int prev = atomicAdd(&g_rowdone[row], 1);
        s_sel = (prev == CHUNKS - 1);
        s_top = 0.f;
    }
    __syncthreads();
    if (!s_sel) return;
    __threadfence();

    // ================= Selection phase (last block of this row) =================
    const int pos_num = *(volatile int*)&g_row_posn[row];
    const int M       = *(volatile int*)&g_cand_n[row];
    const int ovf     = *(volatile int*)&g_row_ovf[row];
    int K = NEG_RATIO * pos_num;
    if (K > NANCH) K = NANCH;

    if (K > 0) {
        if (!ovf && M <= CAP && M >= K) {
            // ---- Fast path: exact top-K over register-resident candidates ----
            unsigned v[16];
            const float* src = g_cand + (size_t)row * CAP;
            unsigned mx = 0u;
            #pragma unroll
            for (int j = 0; j < 16; j++) {
                const int idx = tid + j * T;
                unsigned u = (idx < M) ? __float_as_uint(((const volatile float*)src)[idx]) : 0u;
                v[j] = u;
                mx = (u > mx) ? u : mx;
            }
            mx = warp_max_u(mx);
            if (lane == 0) s_wi[wid] = (int)mx;
            __syncthreads();
            if (tid < 32) {
                unsigned t = (lane < NW) ? (unsigned)s_wi[lane] : 0u;
                t = warp_max_u(t);
                if (lane == 0) { s_lo = P0BITS; s_hi = t + 1u; }
            }
            __syncthreads();

            for (int s = 0; s < 48; s++) {
                const unsigned lo = s_lo, hi = s_hi;
                const unsigned w = hi - lo;
                if (w <= 1u) break;
                const unsigned d = w / 3u;
                const unsigned b1 = lo + (d > 1u ? d : 1u);
                unsigned t2 = 2u * d;
                if (t2 < 2u) t2 = 2u;
                if (t2 > w - 1u) t2 = w - 1u;
                const unsigned b2 = lo + t2;

                int c12 = 0;
                #pragma unroll
                for (int j = 0; j < 16; j++)
                    c12 += (v[j] >= b1) + ((v[j] >= b2) ? 0x10000 : 0);
                c12 = warp_sum_i(c12);
                if (lane == 0) s_wi[wid] = c12;
                __syncthreads();
                if (tid < 32) {
                    int t = (lane < NW) ? s_wi[lane] : 0;
                    t = warp_sum_i(t);
                    if (lane == 0) {
                        const int C1 = t & 0xFFFF;
                        const int C2 = t >> 16;
                        if (C2 >= K)      s_lo = b2;
                        else if (C1 >= K) { s_lo = b1; s_hi = b2; }
                        else              s_hi = b1;
                    }
                }
                __syncthreads();
            }
            const unsigned lo = s_lo;
            float sa = 0.f;
            int ca = 0;
            #pragma unroll
            for (int j = 0; j < 16; j++)
                if (v[j] > lo) { sa += __uint_as_float(v[j]); ca++; }
            sa = warp_sum(sa);
            ca = warp_sum_i(ca);
            if (lane == 0) { s_wf[wid] = sa; s_wi[wid] = ca; }
            __syncthreads();
            if (tid < 32) {
                float fs = (lane < NW) ? s_wf[lane] : 0.f;
                int   cs = (lane < NW) ? s_wi[lane] : 0;
                fs = warp_sum(fs);
                cs = warp_sum_i(cs);
                if (lane == 0) s_top = fs + (float)(K - cs) * __uint_as_float(lo);
            }
            __syncthreads();
        } else {
            // ---- Exact fallback over the full row (statistically never taken) ----
            int K_eff = NANCH - pos_num;
            if (K < K_eff) K_eff = K;
            if (K_eff > 0) {
                if (tid == 0) { s_lo = 0u; s_hi = 0x7F800000u; }
                __syncthreads();
                for (int s = 0; s < 64; s++) {
                    const unsigned lo = s_lo, hi = s_hi;
                    const unsigned w = hi - lo;
                    if (w <= 1u) break;
                    const unsigned d = w / 3u;
                    const unsigned b1 = lo + (d > 1u ? d : 1u);
                    unsigned t2 = 2u * d;
                    if (t2 < 2u) t2 = 2u;
                    if (t2 > w - 1u) t2 = w - 1u;
                    const unsigned b2 = lo + t2;

                    int c12 = 0;
                    for (int i4 = tid; i4 < NQ; i4 += T) {
                        float4 xv = pl4[i4];
                        float4 yv = gl4[i4];
                        #pragma unroll
                        for (int c = 0; c < 4; c++) {
                            float x = (c == 0) ? xv.x : (c == 1) ? xv.y : (c == 2) ? xv.z : xv.w;
                            float y = (c == 0) ? yv.x : (c == 1) ? yv.y : (c == 2) ? yv.z : yv.w;
                            if (!(y > 0.f)) {
                                unsigned u = __float_as_uint(bce_of(x, y));
                                c12 += (u >= b1) + ((u >= b2) ? 0x10000 : 0);
                            }
                        }
                    }
                    c12 = warp_sum_i(c12);
                    if (lane == 0) s_wi[wid] = c12;
                    __syncthreads();
                    if (tid < 32) {
                        int t = (lane < NW) ? s_wi[lane] : 0;
                        t = warp_sum_i(t);
                        if (lane == 0) {
                            const int C1 = t & 0xFFFF;
                            const int C2 = t >> 16;
                            if (C2 >= K_eff)      s_lo = b2;
                            else if (C1 >= K_eff) { s_lo = b1; s_hi = b2; }
                            else                  s_hi = b1;
                        }
                    }
                    __syncthreads();
                }
                const unsigned lo = s_lo;
                float sa = 0.f;
                int ca = 0;
                for (int i4 = tid; i4 < NQ; i4 += T) {
                    float4 xv = pl4[i4];
                    float4 yv = gl4[i4];
                    #pragma unroll
                    for (int c = 0; c < 4; c++) {
                        float x = (c == 0) ? xv.x : (c == 1) ? xv.y : (c == 2) ? xv.z : xv.w;
                        float y = (c == 0) ? yv.x : (c == 1) ? yv.y : (c == 2) ? yv.z : yv.w;
                        if (!(y > 0.f)) {
                            unsigned u = __float_as_uint(bce_of(x, y));
                            if (u > lo) { sa += __uint_as_float(u); ca++; }
                        }
                    }
                }
                sa = warp_sum(sa);
                ca = warp_sum_i(ca);
                if (lane == 0) { s_wf[wid] = sa; s_wi[wid] = ca; }
                __syncthreads();
                if (tid < 32) {
                    float fs = (lane < NW) ? s_wf[lane] : 0.f;
                    int   cs = (lane < NW) ? s_wi[lane] : 0;
                    fs = warp_sum(fs);
                    cs = warp_sum_i(cs);
                    if (lane == 0) s_top = fs + (float)(K_eff - cs) * __uint_as_float(lo);
                }
                __syncthreads();
            }
        }
    }

    // publish row; last row's selector does the final reduction
    if (tid == 0) {
        g_row_lossl[row] = *(volatile float*)&g_row_bcepos[row] + s_top;
        __threadfence();
        int prev = atomicAdd(&g_done, 1);
        s_last = (prev == BATCH - 1);
    }
    __syncthreads();
    if (!s_last) return;
    __threadfence();

    // ================= Final reduction + scratch reset =================
    {
        float vlb = 0.f, vll = 0.f, vm = 0.f;
        if (tid < BATCH) {
            float pn  = (float)((volatile int*)g_row_posn)[tid];
            float lbv = ((volatile float*)g_row_lossb)[tid];
            float llv = ((volatile float*)g_row_lossl)[tid];
            float mask = (pn > 0.f) ? 1.f : 0.f;
            float wgt  = mask / fmaxf(pn, FLT_EPS_);
            vlb = lbv * wgt;
            vll = llv * wgt;
            vm  = wgt;
            // reset per-row scratch for the next graph replay
            g_row_posn[tid]   = 0;
            g_row_lossb[tid]  = 0.f;
            g_row_bcepos[tid] = 0.f;
            g_cand_n[tid]     = 0;
            g_row_ovf[tid]    = 0;
            g_rowdone[tid]    = 0;
        }
        vlb = warp_sum(vlb);
        vll = warp_sum(vll);
        vm  = warp_sum(vm);
        if (lane == 0) {
            s_red[wid * 3 + 0] = vlb;
            s_red[wid * 3 + 1] = vll;
            s_red[wid * 3 + 2] = vm;
        }
        __syncthreads();
        if (tid == 0) {
            float slb = 0.f, sll = 0.f, sm = 0.f;
            #pragma unroll
            for (int w = 0; w < NW; w++) {
                slb += s_red[w * 3 + 0];
                sll += s_red[w * 3 + 1];
                sm  += s_red[w * 3 + 2];
            }
            const float lb = slb / (float)BATCH;
            const float ll = sll / (float)BATCH;
            const float total = (lb + ll) * (sm / (float)BATCH);
            if (out_size >= 1) out[0] = total;
            if (out_size >= 2) out[1] = lb;
            if (out_size >= 3) out[2] = ll;
            g_done = 0;
        }
    }
}

extern "C" void kernel_launch(void* const* d_in, const int* in_sizes, int n_in,
                              void* d_out, int out_size) {
    const float* pbboxs  = (const float*)d_in[0];
    const float* plabels = (const float*)d_in[1];
    const float* gbboxs  = (const float*)d_in[2];
    const float* glabels = (const float*)d_in[3];
    const float* ancs    = (const float*)d_in[4];
    (void)in_sizes; (void)n_in;

    dim3 grid(CHUNKS, BATCH);
    od_main<<<grid, T>>>(pbboxs, plabels, gbboxs, glabels, ancs,
                         (float*)d_out, out_size);
}

// round 10
// speedup vs baseline: 1.1438x; 1.1438x over previous
#include <cuda_runtime.h>
#include <stdint.h>

#define BATCH 128
#define NANCH 16800
#define NQ 4200               // float4 per row
#define CHUNKS 8
#define CQ 525                // float4 per chunk
#define T 256
#define NW (T / 32)           // 8 warps
#define NEL 3                 // ceil(CQ / T)
#define NEG_RATIO 3
#define SCALE_XY 10.0f
#define SCALE_WH 5.0f
#define CAP 4096
#define P0F 1.4f
#define P0BITS 0x3FB33333u    // __float_as_uint(1.4f)
#define HBSHIFT 13
#define HBINS 4096
#define HBASE (P0BITS >> HBSHIFT)
#define CHB 16                // HBINS / T
#define TIE_CAP 128
#define FLT_EPS_ 1.1920929e-07f

// Cross-block scratch (allocation-free rule: __device__ globals; zero-init, reset per replay)
__device__ float g_row_lossb[BATCH];
__device__ float g_row_bcepos[BATCH];
__device__ float g_row_lossl[BATCH];
__device__ int   g_row_posn[BATCH];
__device__ int   g_cand_n[BATCH];
__device__ int   g_row_ovf[BATCH];
__device__ int   g_rowdone[BATCH];
__device__ int   g_done = 0;
__device__ float g_cand[BATCH * CAP];   // 2 MB

__device__ __forceinline__ float warp_sum(float v) {
    #pragma unroll
    for (int o = 16; o > 0; o >>= 1) v += __shfl_down_sync(0xFFFFFFFFu, v, o);
    return v;
}
__device__ __forceinline__ int warp_sum_i(int v) {
    #pragma unroll
    for (int o = 16; o > 0; o >>= 1) v += __shfl_down_sync(0xFFFFFFFFu, v, o);
    return v;
}
// suffix-inclusive scan within warp: result(lane) = sum over lanes >= lane
__device__ __forceinline__ int warp_suffix_incl_i(int v, int lane) {
    #pragma unroll
    for (int o = 1; o < 32; o <<= 1) {
        int u = __shfl_down_sync(0xFFFFFFFFu, v, o);
        if (lane + o < 32) v += u;
    }
    return v;
}
__device__ __forceinline__ float bce_of(float x, float y) {
    return fmaxf(x, 0.f) - x * y + __logf(1.f + __expf(-fabsf(x)));
}

__global__ __launch_bounds__(T)
void od_main(const float* __restrict__ pbboxs,
             const float* __restrict__ plabels,
             const float* __restrict__ gbboxs,
             const float* __restrict__ glabels,
             const float* __restrict__ ancs,
             float* __restrict__ out, int out_size) {
    const int row  = blockIdx.y;
    const int tid  = threadIdx.x;
    const int lane = tid & 31;
    const int wid  = tid >> 5;
    const int qbase = blockIdx.x * CQ;

    __shared__ int      s_hist[HBINS];      // 16 KB (selector only)
    __shared__ unsigned s_tie[TIE_CAP];
    __shared__ float    s_wf[NW], s_wf2[NW];
    __shared__ int      s_wi[NW], s_wsuf[NW];
    __shared__ int      s_sel, s_last, s_tbin, s_tn;
    __shared__ unsigned s_lo, s_hi;
    __shared__ float    s_top;
    __shared__ float    s_red[NW * 3];

    const float4* pl4 = (const float4*)(plabels + (size_t)row * NANCH);
    const float4* gl4 = (const float4*)(glabels + (size_t)row * NANCH);
    const float4* pb  = (const float4*)pbboxs + (size_t)row * NANCH;
    const float4* gb  = (const float4*)gbboxs + (size_t)row * NANCH;
    const float4* an  = (const float4*)ancs;

    // ================= Streaming phase =================
    float bcv[NEL * 4];
    unsigned cm = 0;                      // candidate bit per element
    float acc_sl1 = 0.f, acc_bce = 0.f;
    int cnt = 0;

    #pragma unroll
    for (int it = 0; it < NEL; it++) {
        const int loc = tid + it * T;
        const int i4  = qbase + loc;
        const bool valid = (loc < CQ);
        float4 xv = valid ? pl4[i4] : make_float4(0.f, 0.f, 0.f, 0.f);
        float4 yv = valid ? gl4[i4] : make_float4(0.f, 0.f, 0.f, 0.f);
        #pragma unroll
        for (int c = 0; c < 4; c++) {
            float x = (c == 0) ? xv.x : (c == 1) ? xv.y : (c == 2) ? xv.z : xv.w;
            float y = (c == 0) ? yv.x : (c == 1) ? yv.y : (c == 2) ? yv.z : yv.w;
            float bce = bce_of(x, y);     // invalid lanes: x=y=0 -> bce=ln2 < P0, y=0 -> not pos
            if (y > 0.f) {
                const int i = i4 * 4 + c;
                float4 p = pb[i];
                float4 g = gb[i];
                float4 a = an[i];
                float inv_az = 1.f / a.z;
                float inv_aw = 1.f / a.w;
                float d0 = p.x - SCALE_XY * (g.x - a.x) * inv_az;
                float d1 = p.y - SCALE_XY * (g.y - a.y) * inv_aw;
                float d2 = p.z - SCALE_WH * __logf(g.z * inv_az);
                float d3 = p.w - SCALE_WH * __logf(g.w * inv_aw);
                float sl1 = 0.f, ad;
                ad = fabsf(d0); sl1 += (ad < 1.f) ? 0.5f * d0 * d0 : ad - 0.5f;
                ad = fabsf(d1); sl1 += (ad < 1.f) ? 0.5f * d1 * d1 : ad - 0.5f;
                ad = fabsf(d2); sl1 += (ad < 1.f) ? 0.5f * d2 * d2 : ad - 0.5f;
                ad = fabsf(d3); sl1 += (ad < 1.f) ? 0.5f * d3 * d3 : ad - 0.5f;
                acc_sl1 += sl1;
                acc_bce += bce;
                cnt++;
            } else if (bce >= P0F) {
                cm |= 1u << (it * 4 + c);
            }
            bcv[it * 4 + c] = bce;
        }
    }

    // warp-level candidate compaction: ONE global atomic per warp
    {
        unsigned mks[NEL * 4];
        int wcnt = 0;
        #pragma unroll
        for (int e = 0; e < NEL * 4; e++) {
            mks[e] = __ballot_sync(0xFFFFFFFFu, (cm >> e) & 1u);
            wcnt += __popc(mks[e]);
        }
        if (wcnt > 0) {
            int base = 0;
            if (lane == 0) base = atomicAdd(&g_cand_n[row], wcnt);
            base = __shfl_sync(0xFFFFFFFFu, base, 0);
            float* dst = g_cand + (size_t)row * CAP;
            int off = base;
            #pragma unroll
            for (int e = 0; e < NEL * 4; e++) {
                if ((cm >> e) & 1u) {
                    const int pi = off + __popc(mks[e] & ((1u << lane) - 1u));
                    if (pi < CAP) dst[pi] = bcv[e];
                    else g_row_ovf[row] = 1;
                }
                off += __popc(mks[e]);
            }
        }
    }

    // row scalar accumulation: block reduce -> 3 global atomics
    {
        float w1 = warp_sum(acc_sl1);
        float w2 = warp_sum(acc_bce);
        int   w3 = warp_sum_i(cnt);
        if (lane == 0) { s_wf[wid] = w1; s_wf2[wid] = w2; s_wi[wid] = w3; }
    }
    __syncthreads();
    if (tid == 0) {
        float s1 = 0.f, s2 = 0.f; int s3 = 0;
        #pragma unroll
        for (int i = 0; i < NW; i++) { s1 += s_wf[i]; s2 += s_wf2[i]; s3 += s_wi[i]; }
        if (s1 != 0.f) atomicAdd(&g_row_lossb[row], s1);
        if (s2 != 0.f) atomicAdd(&g_row_bcepos[row], s2);
        if (s3 != 0)   atomicAdd(&g_row_posn[row], s3);
        __threadfence();
        int prev = atomicAdd(&g_rowdone[row], 1);
        s_sel = (prev == CHUNKS - 1);
        s_top = 0.f;
        s_tn  = 0;
    }
    __syncthreads();
    if (!s_sel) return;
    __threadfence();

    // ================= Selection phase (last block of this row) =================
    const int pos_num = *(volatile int*)&g_row_posn[row];
    const int M       = *(volatile int*)&g_cand_n[row];
    const int ovf     = *(volatile int*)&g_row_ovf[row];
    int K = NEG_RATIO * pos_num;
    if (K > NANCH) K = NANCH;

    if (K > 0) {
        if (!ovf && M <= CAP && M >= K) {
            // ---- Fast path: one-shot 4096-bin histogram select over candidates ----
            #pragma unroll
            for (int j = 0; j < CHB; j++) s_hist[tid + j * T] = 0;
            __syncthreads();

            unsigned v[16];
            const volatile float* src = g_cand + (size_t)row * CAP;
            #pragma unroll
            for (int j = 0; j < 16; j++) {
                const int idx = tid + j * T;
                if (idx < M) {
                    unsigned u = __float_as_uint(src[idx]);
                    v[j] = u;
                    unsigned bin = (u >> HBSHIFT) - HBASE;
                    if (bin > HBINS - 1) bin = HBINS - 1;
                    atomicAdd(&s_hist[bin], 1);
                } else {
                    v[j] = 0u;
                }
            }
            __syncthreads();

            // cooperative suffix-scan: find threshold bin (contiguous chunks, high tid = high bins)
            const int base = tid * CHB;
            int lc[CHB];
            int tot = 0;
            #pragma unroll
            for (int j = 0; j < CHB; j++) { lc[j] = s_hist[base + j]; tot += lc[j]; }
            int incl = warp_suffix_incl_i(tot, lane);
            if (lane == 0) s_wi[wid] = incl;
            __syncthreads();
            if (tid < 32) {
                int wv = (lane < NW) ? s_wi[lane] : 0;
                int wi = warp_suffix_incl_i(wv, lane);
                if (lane < NW) s_wsuf[lane] = wi - wv;  // counts in warps above
            }
            __syncthreads();
            const int excl = (incl - tot) + s_wsuf[wid];
            if (excl < K && excl + tot >= K) {
                int cum = excl;
                #pragma unroll
                for (int j = CHB - 1; j >= 0; j--) {
                    cum += lc[j];
                    if (cum >= K) { s_tbin = base + j; break; }
                }
            }
            __syncthreads();
            const int tbin = s_tbin;

            // exact above-sum + gather tie-bin values
            float sa = 0.f;
            int ca = 0;
            #pragma unroll
            for (int j = 0; j < 16; j++) {
                const unsigned u = v[j];
                if (tid + j * T < M) {
                    int bin = (int)((u >> HBSHIFT) - HBASE);
                    if (bin > HBINS - 1) bin = HBINS - 1;
                    if (bin > tbin) { sa += __uint_as_float(u); ca++; }
                    else if (bin == tbin) {
                        int pi = atomicAdd(&s_tn, 1);
                        if (pi < TIE_CAP) s_tie[pi] = u;
                    }
                }
            }
            sa = warp_sum(sa);
            ca = warp_sum_i(ca);
            if (lane == 0) { s_wf[wid] = sa; s_wi[wid] = ca; }
            __syncthreads();
            if (tid == 0) {
                float fs = 0.f; int cs = 0;
                #pragma unroll
                for (int i = 0; i < NW; i++) { fs += s_wf[i]; cs += s_wi[i]; }
                int kr = K - cs;                 // copies to take from tie bin
                const int tn = s_tn;
                float tadd = 0.f;
                if (kr > 0) {
                    if (tn <= TIE_CAP) {
                        // exact: selection-sort top kr of the (tiny) tie set
                        for (int a = 0; a < kr; a++) {
                            int mi = a;
                            for (int z = a + 1; z < tn; z++)
                                if (s_tie[z] > s_tie[mi]) mi = z;
                            unsigned tv = s_tie[mi];
                            s_tie[mi] = s_tie[a];
                            s_tie[a] = tv;
                            tadd += __uint_as_float(tv);
                        }
                    } else {
                        // overflow (statistically never): average approximation
                        float ts = 0.f;
                        for (int z = 0; z < TIE_CAP; z++) ts += __uint_as_float(s_tie[z]);
                        tadd = (float)kr * (ts / (float)TIE_CAP);
                    }
                }
                s_top = fs + tadd;
            }
            __syncthreads();
        } else {
            // ---- Exact fallback over the full row (statistically never taken) ----
            int K_eff = NANCH - pos_num;
            if (K < K_eff) K_eff = K;
            if (K_eff > 0) {
                if (tid == 0) { s_lo = 0u; s_hi = 0x7F800000u; }
                __syncthreads();
                for (int s = 0; s < 64; s++) {
                    const unsigned lo = s_lo, hi = s_hi;
                    const unsigned w = hi - lo;
                    if (w <= 1u) break;
                    const unsigned d = w / 3u;
                    const unsigned b1 = lo + (d > 1u ? d : 1u);
                    unsigned t2 = 2u * d;
                    if (t2 < 2u) t2 = 2u;
                    if (t2 > w - 1u) t2 = w - 1u;
                    const unsigned b2 = lo + t2;

                    int c12 = 0;
                    for (int i4 = tid; i4 < NQ; i4 += T) {
                        float4 xv = pl4[i4];
                        float4 yv = gl4[i4];
                        #pragma unroll
                        for (int c = 0; c < 4; c++) {
                            float x = (c == 0) ? xv.x : (c == 1) ? xv.y : (c == 2) ? xv.z : xv.w;
                            float y = (c == 0) ? yv.x : (c == 1) ? yv.y : (c == 2) ? yv.z : yv.w;
                            if (!(y > 0.f)) {
                                unsigned u = __float_as_uint(bce_of(x, y));
                                c12 += (u >= b1) + ((u >= b2) ? 0x10000 : 0);
                            }
                        }
                    }
                    c12 = warp_sum_i(c12);
                    if (lane == 0) s_wi[wid] = c12;
                    __syncthreads();
                    if (tid == 0) {
                        int t = 0;
                        #pragma unroll
                        for (int i = 0; i < NW; i++) t += s_wi[i];
                        const int C1 = t & 0xFFFF;
                        const int C2 = t >> 16;
                        if (C2 >= K_eff)      s_lo = b2;
                        else if (C1 >= K_eff) { s_lo = b1; s_hi = b2; }
                        else                  s_hi = b1;
                    }
                    __syncthreads();
                }
                const unsigned lo = s_lo;
                float sa = 0.f;
                int ca = 0;
                for (int i4 = tid; i4 < NQ; i4 += T) {
                    float4 xv = pl4[i4];
                    float4 yv = gl4[i4];
                    #pragma unroll
                    for (int c = 0; c < 4; c++) {
                        float x = (c == 0) ? xv.x : (c == 1) ? xv.y : (c == 2) ? xv.z : xv.w;
                        float y = (c == 0) ? yv.x : (c == 1) ? yv.y : (c == 2) ? yv.z : yv.w;
                        if (!(y > 0.f)) {
                            unsigned u = __float_as_uint(bce_of(x, y));
                            if (u > lo) { sa += __uint_as_float(u); ca++; }
                        }
                    }
                }
                sa = warp_sum(sa);
                ca = warp_sum_i(ca);
                if (lane == 0) { s_wf[wid] = sa; s_wi[wid] = ca; }
                __syncthreads();
                if (tid == 0) {
                    float fs = 0.f; int cs = 0;
                    #pragma unroll
                    for (int i = 0; i < NW; i++) { fs += s_wf[i]; cs += s_wi[i]; }
                    s_top = fs + (float)(K_eff - cs) * __uint_as_float(lo);
                }
                __syncthreads();
            }
        }
    }

    // publish row; last selector does the final reduction
    if (tid == 0) {
        g_row_lossl[row] = *(volatile float*)&g_row_bcepos[row] + s_top;
        __threadfence();
        int prev = atomicAdd(&g_done, 1);
        s_last = (prev == BATCH - 1);
    }
    __syncthreads();
    if (!s_last) return;
    __threadfence();

    // ================= Final reduction + scratch reset =================
    {
        float vlb = 0.f, vll = 0.f, vm = 0.f;
        if (tid < BATCH) {
            float pn  = (float)((volatile int*)g_row_posn)[tid];
            float lbv = ((volatile float*)g_row_lossb)[tid];
            float llv = ((volatile float*)g_row_lossl)[tid];
            float mask = (pn > 0.f) ? 1.f : 0.f;
            float wgt  = mask / fmaxf(pn, FLT_EPS_);
            vlb = lbv * wgt;
            vll = llv * wgt;
            vm  = wgt;
            // reset per-row scratch for the next graph replay
            g_row_posn[tid]   = 0;
            g_row_lossb[tid]  = 0.f;
            g_row_bcepos[tid] = 0.f;
            g_cand_n[tid]     = 0;
            g_row_ovf[tid]    = 0;
            g_rowdone[tid]    = 0;
        }
        vlb = warp_sum(vlb);
        vll = warp_sum(vll);
        vm  = warp_sum(vm);
        if (lane == 0) {
            s_red[wid * 3 + 0] = vlb;
            s_red[wid * 3 + 1] = vll;
            s_red[wid * 3 + 2] = vm;
        }
        __syncthreads();
        if (tid == 0) {
            float slb = 0.f, sll = 0.f, sm = 0.f;
            #pragma unroll
            for (int w = 0; w < NW; w++) {
                slb += s_red[w * 3 + 0];
                sll += s_red[w * 3 + 1];
                sm  += s_red[w * 3 + 2];
            }
            const float lb = slb / (float)BATCH;
            const float ll = sll / (float)BATCH;
            const float total = (lb + ll) * (sm / (float)BATCH);
            if (out_size >= 1) out[0] = total;
            if (out_size >= 2) out[1] = lb;
            if (out_size >= 3) out[2] = ll;
            g_done = 0;
        }
    }
}

extern "C" void kernel_launch(void* const* d_in, const int* in_sizes, int n_in,
                              void* d_out, int out_size) {
    const float* pbboxs  = (const float*)d_in[0];
    const float* plabels = (const float*)d_in[1];
    const float* gbboxs  = (const float*)d_in[2];
    const float* glabels = (const float*)d_in[3];
    const float* ancs    = (const float*)d_in[4];
    (void)in_sizes; (void)n_in;

    dim3 grid(CHUNKS, BATCH);
    od_main<<<grid, T>>>(pbboxs, plabels, gbboxs, glabels, ancs,
                         (float*)d_out, out_size);
}

// round 11
// speedup vs baseline: 1.7360x; 1.5178x over previous
#include <cuda_runtime.h>
#include <stdint.h>

#define BATCH 128
#define NANCH 16800
#define NQ 4200               // float4 per row
#define T 1024
#define NW 32
#define NIT 5                 // ceil(NQ / T)
#define NEG_RATIO 3
#define SCALE_XY 10.0f
#define SCALE_WH 5.0f
#define CAP 4096
#define XCF 1.1f              // x cutoff; softplus(1.1)=1.387 << typical Kth value ~1.9
#define HBSHIFT 13
#define HBINS 4096            // bins over x in [1.0, 16.0)
#define HBASE (0x3F800000u >> HBSHIFT)
#define CHB 4                 // HBINS / T
#define TIE_CAP 64
#define FLT_EPS_ 1.1920929e-07f

// Cross-block scratch (allocation-free rule: __device__ globals)
__device__ float g_row_lossb[BATCH];
__device__ float g_row_lossl[BATCH];
__device__ int   g_row_posn[BATCH];
__device__ int   g_done = 0;

__device__ __forceinline__ float warp_sum(float v) {
    #pragma unroll
    for (int o = 16; o > 0; o >>= 1) v += __shfl_down_sync(0xFFFFFFFFu, v, o);
    return v;
}
__device__ __forceinline__ int warp_sum_i(int v) {
    #pragma unroll
    for (int o = 16; o > 0; o >>= 1) v += __shfl_down_sync(0xFFFFFFFFu, v, o);
    return v;
}
// suffix-inclusive scan within warp: result(lane) = sum over lanes >= lane
__device__ __forceinline__ int warp_suffix_incl_i(int v, int lane) {
    #pragma unroll
    for (int o = 1; o < 32; o <<= 1) {
        int u = __shfl_down_sync(0xFFFFFFFFu, v, o);
        if (lane + o < 32) v += u;
    }
    return v;
}
__device__ __forceinline__ float bce_of(float x, float y) {
    return fmaxf(x, 0.f) - x * y + __logf(1.f + __expf(-fabsf(x)));
}
// bce for a negative (y=0) with x > 0: softplus(x)
__device__ __forceinline__ float bce_neg_pos_x(float x) {
    return x + __logf(1.f + __expf(-x));
}
// order-preserving map for signed float bits
__device__ __forceinline__ unsigned fmap(unsigned b) {
    return (b & 0x80000000u) ? ~b : (b | 0x80000000u);
}

__global__ __launch_bounds__(T, 1)
void od_fused(const float* __restrict__ pbboxs,
              const float* __restrict__ plabels,
              const float* __restrict__ gbboxs,
              const float* __restrict__ glabels,
              const float* __restrict__ ancs,
              float* __restrict__ out, int out_size) {
    const int b    = blockIdx.x;
    const int tid  = threadIdx.x;
    const int lane = tid & 31;
    const int wid  = tid >> 5;

    __shared__ unsigned s_cand[CAP];     // candidate x bit patterns (positive floats)
    __shared__ int      s_hist[HBINS];
    __shared__ unsigned s_tie[TIE_CAP];
    __shared__ float    s_wf[NW], s_wf2[NW];
    __shared__ int      s_wi[NW], s_wsuf[NW];
    __shared__ float    s_sl1, s_bce, s_top;
    __shared__ int      s_cnt, s_m, s_ovf, s_tn, s_tbin, s_last;
    __shared__ unsigned s_lo, s_hi;
    __shared__ float    s_red[NW * 3];

    // init
    #pragma unroll
    for (int j = 0; j < CHB; j++) s_hist[tid + j * T] = 0;
    if (tid == 0) { s_m = 0; s_ovf = 0; s_tn = 0; s_top = 0.f; s_tbin = 0; }
    __syncthreads();

    const float4* pl4 = (const float4*)(plabels + (size_t)b * NANCH);
    const float4* gl4 = (const float4*)(glabels + (size_t)b * NANCH);
    const float4* pb  = (const float4*)pbboxs + (size_t)b * NANCH;
    const float4* gb  = (const float4*)gbboxs + (size_t)b * NANCH;
    const float4* an  = (const float4*)ancs;

    // ---- Main pass: stream x,y; NO transcendentals on the common path ----
    float acc_sl1 = 0.f, acc_bce = 0.f;
    int cnt = 0;

    float4 xv = make_float4(0.f, 0.f, 0.f, 0.f);
    float4 yv = make_float4(0.f, 0.f, 0.f, 0.f);
    {
        const int i4 = tid;
        if (i4 < NQ) { xv = pl4[i4]; yv = gl4[i4]; }
    }
    #pragma unroll
    for (int it = 0; it < NIT; it++) {
        // double-buffer: issue next iter's loads before processing current
        float4 xn = make_float4(0.f, 0.f, 0.f, 0.f);
        float4 yn = make_float4(0.f, 0.f, 0.f, 0.f);
        if (it + 1 < NIT) {
            const int i4n = tid + (it + 1) * T;
            if (i4n < NQ) { xn = pl4[i4n]; yn = gl4[i4n]; }
        }
        const int i4 = tid + it * T;

        float xs[4];
        bool  cand[4];
        #pragma unroll
        for (int c = 0; c < 4; c++) {
            float x = (c == 0) ? xv.x : (c == 1) ? xv.y : (c == 2) ? xv.z : xv.w;
            float y = (c == 0) ? yv.x : (c == 1) ? yv.y : (c == 2) ? yv.z : yv.w;
            xs[c] = x;
            bool pos = (y > 0.f);          // tail lanes: y=0 -> never pos
            cand[c] = (!pos) && (x >= XCF); // tail lanes: x=0 -> never cand
            if (pos) {
                // rare (~2%): bce + box smooth-L1
                acc_bce += bce_of(x, y);
                const int i = (i4 << 2) + c;
                float4 p = pb[i];
                float4 g = gb[i];
                float4 a = an[i];
                float inv_az = 1.f / a.z;
                float inv_aw = 1.f / a.w;
                float d0 = p.x - SCALE_XY * (g.x - a.x) * inv_az;
                float d1 = p.y - SCALE_XY * (g.y - a.y) * inv_aw;
                float d2 = p.z - SCALE_WH * __logf(g.z * inv_az);
                float d3 = p.w - SCALE_WH * __logf(g.w * inv_aw);
                float sl1 = 0.f, ad;
                ad = fabsf(d0); sl1 += (ad < 1.f) ? 0.5f * d0 * d0 : ad - 0.5f;
                ad = fabsf(d1); sl1 += (ad < 1.f) ? 0.5f * d1 * d1 : ad - 0.5f;
                ad = fabsf(d2); sl1 += (ad < 1.f) ? 0.5f * d2 * d2 : ad - 0.5f;
                ad = fabsf(d3); sl1 += (ad < 1.f) ? 0.5f * d3 * d3 : ad - 0.5f;
                acc_sl1 += sl1;
                cnt++;
            }
        }
        // warp-aggregated compaction of candidate x's (store raw bits; x>0 -> monotone)
        unsigned m0 = __ballot_sync(0xFFFFFFFFu, cand[0]);
        unsigned m1 = __ballot_sync(0xFFFFFFFFu, cand[1]);
        unsigned m2 = __ballot_sync(0xFFFFFFFFu, cand[2]);
        unsigned m3 = __ballot_sync(0xFFFFFFFFu, cand[3]);
        int wcnt = __popc(m0) + __popc(m1) + __popc(m2) + __popc(m3);
        if (wcnt > 0) {
            int base = 0;
            if (lane == 0) base = atomicAdd(&s_m, wcnt);
            base = __shfl_sync(0xFFFFFFFFu, base, 0);
            const unsigned lmask = (1u << lane) - 1u;
            int off = base;
            if (cand[0]) { int pi = off + __popc(m0 & lmask); if (pi < CAP) s_cand[pi] = __float_as_uint(xs[0]); else s_ovf = 1; }
            off += __popc(m0);
            if (cand[1]) { int pi = off + __popc(m1 & lmask); if (pi < CAP) s_cand[pi] = __float_as_uint(xs[1]); else s_ovf = 1; }
            off += __popc(m1);
            if (cand[2]) { int pi = off + __popc(m2 & lmask); if (pi < CAP) s_cand[pi] = __float_as_uint(xs[2]); else s_ovf = 1; }
            off += __popc(m2);
            if (cand[3]) { int pi = off + __popc(m3 & lmask); if (pi < CAP) s_cand[pi] = __float_as_uint(xs[3]); else s_ovf = 1; }
        }
        xv = xn; yv = yn;
    }

    // row scalar reduction (no atomics)
    {
        float w1 = warp_sum(acc_sl1);
        float w2 = warp_sum(acc_bce);
        int   w3 = warp_sum_i(cnt);
        if (lane == 0) { s_wf[wid] = w1; s_wf2[wid] = w2; s_wi[wid] = w3; }
    }
    __syncthreads();
    if (tid < 32) {
        float v1 = warp_sum(s_wf[lane]);
        float v2 = warp_sum(s_wf2[lane]);
        int   v3 = warp_sum_i(s_wi[lane]);
        if (lane == 0) { s_sl1 = v1; s_bce = v2; s_cnt = v3; }
    }
    __syncthreads();

    const int pos_num = s_cnt;
    const int M = s_m;
    const bool ovf = (s_ovf != 0);
    int K = NEG_RATIO * pos_num;
    if (K > NANCH) K = NANCH;

    if (K > 0) {
        if (!ovf && M >= K) {
            // ---- Fast path: histogram select on x-bits; bce only for selected ----
            for (int idx = tid; idx < M; idx += T) {
                unsigned u = s_cand[idx];
                unsigned bin = (u >> HBSHIFT) - HBASE;
                if (bin > HBINS - 1) bin = HBINS - 1;
                atomicAdd(&s_hist[bin], 1);
            }
            __syncthreads();

            // suffix-scan over 4096 bins (4 contiguous bins per thread)
            const int base = tid * CHB;
            int lc[CHB];
            int tot = 0;
            #pragma unroll
            for (int j = 0; j < CHB; j++) { lc[j] = s_hist[base + j]; tot += lc[j]; }
            int incl = warp_suffix_incl_i(tot, lane);
            if (lane == 0) s_wi[wid] = incl;
            __syncthreads();
            if (tid < 32) {
                int wv = s_wi[lane];
                int wi = warp_suffix_incl_i(wv, lane);
                s_wsuf[lane] = wi - wv;
            }
            __syncthreads();
            const int excl = (incl - tot) + s_wsuf[wid];
            if (excl < K && excl + tot >= K) {
                int cum = excl;
                #pragma unroll
                for (int j = CHB - 1; j >= 0; j--) {
                    cum += lc[j];
                    if (cum >= K) { s_tbin = base + j; break; }
                }
            }
            __syncthreads();
            const int tbin = s_tbin;

            // exact: bce-sum of candidates above tie bin; gather tie bin
            float sa = 0.f;
            int ca = 0;
            for (int idx = tid; idx < M; idx += T) {
                unsigned u = s_cand[idx];
                int bin = (int)((u >> HBSHIFT) - HBASE);
                if (bin > HBINS - 1) bin = HBINS - 1;
                if (bin > tbin) {
                    sa += bce_neg_pos_x(__uint_as_float(u));  // MUFU only here (~K/1024 per thread)
                    ca++;
                } else if (bin == tbin) {
                    int pi = atomicAdd(&s_tn, 1);
                    if (pi < TIE_CAP) s_tie[pi] = u;
                }
            }
            sa = warp_sum(sa);
            ca = warp_sum_i(ca);
            if (lane == 0) { s_wf[wid] = sa; s_wi[wid] = ca; }
            __syncthreads();
            if (tid == 0) {
                float fs = 0.f; int cs = 0;
                #pragma unroll
                for (int i = 0; i < NW; i++) { fs += s_wf[i]; cs += s_wi[i]; }
                int kr = K - cs;
                const int tn = s_tn;
                float tadd = 0.f;
                if (kr > 0) {
                    if (tn <= TIE_CAP) {
                        // exact: take kr largest x of the tiny tie set
                        for (int a2 = 0; a2 < kr; a2++) {
                            int mi = a2;
                            for (int z = a2 + 1; z < tn; z++)
                                if (s_tie[z] > s_tie[mi]) mi = z;
                            unsigned tv = s_tie[mi];
                            s_tie[mi] = s_tie[a2];
                            s_tie[a2] = tv;
                            tadd += bce_neg_pos_x(__uint_as_float(tv));
                        }
                    } else {
                        float ts = 0.f;
                        for (int z = 0; z < TIE_CAP; z++) ts += bce_neg_pos_x(__uint_as_float(s_tie[z]));
                        tadd = (float)kr * (ts / (float)TIE_CAP);
                    }
                }
                s_top = fs + tadd;
            }
            __syncthreads();
        } else {
            // ---- Exact fallback: binary search on mapped x-bits (never taken) ----
            int K_eff = NANCH - pos_num;
            if (K < K_eff) K_eff = K;
            if (K_eff > 0) {
                if (tid == 0) { s_lo = 0u; s_hi = 0xFFFFFFFFu; }
                __syncthreads();
                for (int s = 0; s < 64; s++) {
                    const unsigned lo = s_lo, hi = s_hi;
                    const unsigned w = hi - lo;
                    if (w <= 1u) break;
                    const unsigned bmid = lo + (w >> 1);
                    int c1 = 0;
                    for (int i4 = tid; i4 < NQ; i4 += T) {
                        float4 xq = pl4[i4];
                        float4 yq = gl4[i4];
                        #pragma unroll
                        for (int c = 0; c < 4; c++) {
                            float x = (c == 0) ? xq.x : (c == 1) ? xq.y : (c == 2) ? xq.z : xq.w;
                            float y = (c == 0) ? yq.x : (c == 1) ? yq.y : (c == 2) ? yq.z : yq.w;
                            if (!(y > 0.f)) c1 += (fmap(__float_as_uint(x)) >= bmid);
                        }
                    }
                    c1 = warp_sum_i(c1);
                    if (lane == 0) s_wi[wid] = c1;
                    __syncthreads();
                    if (tid == 0) {
                        int t = 0;
                        #pragma unroll
                        for (int i = 0; i < NW; i++) t += s_wi[i];
                        if (t >= K_eff) s_lo = bmid; else s_hi = bmid;
                    }
                    __syncthreads();
                }
                const unsigned lo = s_lo;
                float sa = 0.f;
                int ca = 0;
                for (int i4 = tid; i4 < NQ; i4 += T) {
                    float4 xq = pl4[i4];
                    float4 yq = gl4[i4];
                    #pragma unroll
                    for (int c = 0; c < 4; c++) {
                        float x = (c == 0) ? xq.x : (c == 1) ? xq.y : (c == 2) ? xq.z : xq.w;
                        float y = (c == 0) ? yq.x : (c == 1) ? yq.y : (c == 2) ? yq.z : yq.w;
                        if (!(y > 0.f) && fmap(__float_as_uint(x)) > lo) {
                            sa += bce_of(x, 0.f);
                            ca++;
                        }
                    }
                }
                sa = warp_sum(sa);
                ca = warp_sum_i(ca);
                if (lane == 0) { s_wf[wid] = sa; s_wi[wid] = ca; }
                __syncthreads();
                if (tid == 0) {
                    float fs = 0.f; int cs = 0;
                    #pragma unroll
                    for (int i = 0; i < NW; i++) { fs += s_wf[i]; cs += s_wi[i]; }
                    unsigned lb = lo;
                    float xlo = (lb & 0x80000000u) ? __uint_as_float(lb & 0x7FFFFFFFu)
                                                   : __uint_as_float(~lb);
                    s_top = fs + (float)(K_eff - cs) * bce_of(xlo, 0.f);
                }
                __syncthreads();
            }
        }
    }
    const float sum_top = (K > 0) ? s_top : 0.f;

    // ---- Publish row; last block does the final reduction ----
    if (tid == 0) {
        g_row_posn[b]  = pos_num;
        g_row_lossb[b] = s_sl1;
        g_row_lossl[b] = s_bce + sum_top;
        __threadfence();
        int prev = atomicAdd(&g_done, 1);
        s_last = (prev == BATCH - 1);
    }
    __syncthreads();

    if (s_last) {
        float vlb = 0.f, vll = 0.f, vm = 0.f;
        if (tid < BATCH) {
            float pn  = (float)((volatile int*)g_row_posn)[tid];
            float lbv = ((volatile float*)g_row_lossb)[tid];
            float llv = ((volatile float*)g_row_lossl)[tid];
            float mask = (pn > 0.f) ? 1.f : 0.f;
            float wgt  = mask / fmaxf(pn, FLT_EPS_);
            vlb = lbv * wgt;
            vll = llv * wgt;
            vm  = wgt;
        }
        vlb = warp_sum(vlb);
        vll = warp_sum(vll);
        vm  = warp_sum(vm);
        if (lane == 0) {
            s_red[wid * 3 + 0] = vlb;
            s_red[wid * 3 + 1] = vll;
            s_red[wid * 3 + 2] = vm;
        }
        __syncthreads();
        if (tid == 0) {
            float slb = 0.f, sll = 0.f, sm = 0.f;
            #pragma unroll
            for (int w = 0; w < NW; w++) {
                slb += s_red[w * 3 + 0];
                sll += s_red[w * 3 + 1];
                sm  += s_red[w * 3 + 2];
            }
            const float lb = slb / (float)BATCH;
            const float ll = sll / (float)BATCH;
            const float total = (lb + ll) * (sm / (float)BATCH);
            if (out_size >= 1) out[0] = total;
            if (out_size >= 2) out[1] = lb;
            if (out_size >= 3) out[2] = ll;
            g_done = 0;  // reset for next graph replay
        }
    }
}

extern "C" void kernel_launch(void* const* d_in, const int* in_sizes, int n_in,
                              void* d_out, int out_size) {
    const float* pbboxs  = (const float*)d_in[0];
    const float* plabels = (const float*)d_in[1];
    const float* gbboxs  = (const float*)d_in[2];
    const float* glabels = (const float*)d_in[3];
    const float* ancs    = (const float*)d_in[4];
    (void)in_sizes; (void)n_in;

    od_fused<<<BATCH, T>>>(pbboxs, plabels, gbboxs, glabels, ancs,
                           (float*)d_out, out_size);
}